// round 4
// baseline (speedup 1.0000x reference)
#include <cuda_runtime.h>
#include <cuda_bf16.h>
#include <cstdint>

#define NUM_CLASSES 1000
#define FEAT_DIM    256
#define N_ROWS      262144
#define ALPHA       0.5f

// Scratch (device globals — no allocation allowed).
__device__ int g_counts[NUM_CLASSES];
__device__ int g_offsets[NUM_CLASSES];
__device__ int g_cursors[NUM_CLASSES];
__device__ int g_rowidx[N_ROWS];

// ---------------------------------------------------------------------------
// K1: zero the per-class counters (4 KB).
// ---------------------------------------------------------------------------
__global__ void zero_kernel() {
    int i = blockIdx.x * blockDim.x + threadIdx.x;
    if (i < NUM_CLASSES) g_counts[i] = 0;
}

// ---------------------------------------------------------------------------
// K2: histogram of labels.
// ---------------------------------------------------------------------------
__global__ void hist_kernel(const int* __restrict__ labels) {
    int i = blockIdx.x * blockDim.x + threadIdx.x;
    if (i < N_ROWS) atomicAdd(&g_counts[labels[i]], 1);
}

// ---------------------------------------------------------------------------
// K3: exclusive prefix scan over 1000 counts (single block, 1024 threads).
// Writes offsets[] and initializes cursors[] = offsets[].
// ---------------------------------------------------------------------------
__global__ void scan_kernel() {
    __shared__ int sc[1024];
    int tid = threadIdx.x;
    int val = (tid < NUM_CLASSES) ? g_counts[tid] : 0;
    sc[tid] = val;
    __syncthreads();
#pragma unroll
    for (int off = 1; off < 1024; off <<= 1) {
        int t = (tid >= off) ? sc[tid - off] : 0;
        __syncthreads();
        sc[tid] += t;
        __syncthreads();
    }
    if (tid < NUM_CLASSES) {
        int excl = sc[tid] - val;  // exclusive scan
        g_offsets[tid] = excl;
        g_cursors[tid] = excl;
    }
}

// ---------------------------------------------------------------------------
// K4: scatter row indices into class-sorted order.
// ---------------------------------------------------------------------------
__global__ void scatter_kernel(const int* __restrict__ labels) {
    int i = blockIdx.x * blockDim.x + threadIdx.x;
    if (i < N_ROWS) {
        int cls = labels[i];
        int pos = atomicAdd(&g_cursors[cls], 1);
        g_rowidx[pos] = i;
    }
}

// ---------------------------------------------------------------------------
// K5: one block per class — gather-sum rows (no atomics), fused mean + EMA.
// 256 threads: tid -> (row-slot r4 in 0..3, float4 column c4 in 0..63).
// ---------------------------------------------------------------------------
#define F4ADD(a, b) { (a).x += (b).x; (a).y += (b).y; (a).z += (b).z; (a).w += (b).w; }

__global__ void sum_ema_kernel(const float* __restrict__ features,
                               const float* __restrict__ centers,
                               float* __restrict__ out) {
    int cls = blockIdx.x;
    int n = g_counts[cls];
    int start = g_offsets[cls];
    int tid = threadIdx.x;
    int r4 = tid >> 6;   // row slot 0..3
    int c4 = tid & 63;   // float4 column 0..63

    __shared__ float4 s[256];
    const float4* __restrict__ f4 = reinterpret_cast<const float4*>(features);
    const int* __restrict__ ridx = g_rowidx + start;

    float4 a0 = make_float4(0.f, 0.f, 0.f, 0.f);
    float4 a1 = a0, a2 = a0, a3 = a0;

    int i = r4;
    // 4-deep unroll: 16 rows in flight per block iteration.
    for (; i + 12 < n; i += 16) {
        int i0 = ridx[i];
        int i1 = ridx[i + 4];
        int i2 = ridx[i + 8];
        int i3 = ridx[i + 12];
        float4 v0 = f4[(size_t)i0 * 64 + c4];
        float4 v1 = f4[(size_t)i1 * 64 + c4];
        float4 v2 = f4[(size_t)i2 * 64 + c4];
        float4 v3 = f4[(size_t)i3 * 64 + c4];
        F4ADD(a0, v0); F4ADD(a1, v1); F4ADD(a2, v2); F4ADD(a3, v3);
    }
    for (; i < n; i += 4) {
        int r = ridx[i];
        float4 v = f4[(size_t)r * 64 + c4];
        F4ADD(a0, v);
    }
    F4ADD(a0, a1); F4ADD(a2, a3); F4ADD(a0, a2);

    s[tid] = a0;
    __syncthreads();

    if (tid < 64) {
        float4 t0 = s[tid];
        float4 t1 = s[tid + 64];
        float4 t2 = s[tid + 128];
        float4 t3 = s[tid + 192];
        F4ADD(t0, t1); F4ADD(t2, t3); F4ADD(t0, t2);

        float4 c = reinterpret_cast<const float4*>(centers)[(size_t)cls * 64 + tid];
        float4 o;
        if (n > 0) {
            float scale = ALPHA / (float)n;   // ALPHA * mean
            o.x = (1.0f - ALPHA) * c.x + scale * t0.x;
            o.y = (1.0f - ALPHA) * c.y + scale * t0.y;
            o.z = (1.0f - ALPHA) * c.z + scale * t0.z;
            o.w = (1.0f - ALPHA) * c.w + scale * t0.w;
        } else {
            o = c;
        }
        reinterpret_cast<float4*>(out)[(size_t)cls * 64 + tid] = o;
    }
}

// ---------------------------------------------------------------------------
// Launch: features f32 [N,256], labels i32 [N], centers f32 [1000,256].
// ---------------------------------------------------------------------------
extern "C" void kernel_launch(void* const* d_in, const int* in_sizes, int n_in,
                              void* d_out, int out_size) {
    const float* features = (const float*)d_in[0];
    const int* labels     = (const int*)d_in[1];
    const float* centers  = (const float*)d_in[2];
    float* out            = (float*)d_out;

    zero_kernel<<<(NUM_CLASSES + 255) / 256, 256>>>();
    hist_kernel<<<(N_ROWS + 255) / 256, 256>>>(labels);
    scan_kernel<<<1, 1024>>>();
    scatter_kernel<<<(N_ROWS + 255) / 256, 256>>>(labels);
    sum_ema_kernel<<<NUM_CLASSES, 256>>>(features, centers, out);
}

// round 5
// speedup vs baseline: 1.4980x; 1.4980x over previous
#include <cuda_runtime.h>
#include <cuda_bf16.h>
#include <cstdint>

#define NUM_CLASSES 1000
#define FEAT_DIM    256
#define N_ROWS      262144
#define ALPHA       0.5f
#define PAD         32          // one counter per 128-byte L2 line

// Scratch (device globals — no allocation allowed).
__device__ int g_counts[NUM_CLASSES * PAD];    // padded: index cls*PAD
__device__ int g_cursors[NUM_CLASSES * PAD];   // padded
__device__ int g_offsets[NUM_CLASSES];
__device__ int g_rowidx[N_ROWS];

// ---------------------------------------------------------------------------
// K1: zero the padded per-class counters (128 KB).
// ---------------------------------------------------------------------------
__global__ void zero_kernel() {
    int i = blockIdx.x * blockDim.x + threadIdx.x;
    if (i < NUM_CLASSES * PAD) g_counts[i] = 0;
}

// ---------------------------------------------------------------------------
// K2: histogram of labels (atomics spread over 184 LTS slices via padding).
// ---------------------------------------------------------------------------
__global__ void hist_kernel(const int* __restrict__ labels) {
    int i = blockIdx.x * blockDim.x + threadIdx.x;
    if (i < N_ROWS) atomicAdd(&g_counts[labels[i] * PAD], 1);
}

// ---------------------------------------------------------------------------
// K3: exclusive prefix scan over 1000 counts (single block, 1024 threads).
// Writes offsets[] and initializes padded cursors[].
// ---------------------------------------------------------------------------
__global__ void scan_kernel() {
    __shared__ int sc[1024];
    int tid = threadIdx.x;
    int val = (tid < NUM_CLASSES) ? g_counts[tid * PAD] : 0;
    sc[tid] = val;
    __syncthreads();
#pragma unroll
    for (int off = 1; off < 1024; off <<= 1) {
        int t = (tid >= off) ? sc[tid - off] : 0;
        __syncthreads();
        sc[tid] += t;
        __syncthreads();
    }
    if (tid < NUM_CLASSES) {
        int excl = sc[tid] - val;  // exclusive scan
        g_offsets[tid] = excl;
        g_cursors[tid * PAD] = excl;
    }
}

// ---------------------------------------------------------------------------
// K4: scatter row indices into class-sorted order (padded cursors).
// ---------------------------------------------------------------------------
__global__ void scatter_kernel(const int* __restrict__ labels) {
    int i = blockIdx.x * blockDim.x + threadIdx.x;
    if (i < N_ROWS) {
        int cls = labels[i];
        int pos = atomicAdd(&g_cursors[cls * PAD], 1);
        g_rowidx[pos] = i;
    }
}

// ---------------------------------------------------------------------------
// K5: one block per class — gather-sum rows (no atomics), fused mean + EMA.
// 256 threads: tid -> (row-slot r4 in 0..3, float4 column c4 in 0..63).
// 8-deep unroll: 32 rows in flight per block.
// ---------------------------------------------------------------------------
#define F4ADD(a, b) { (a).x += (b).x; (a).y += (b).y; (a).z += (b).z; (a).w += (b).w; }

__global__ void sum_ema_kernel(const float* __restrict__ features,
                               const float* __restrict__ centers,
                               float* __restrict__ out) {
    int cls = blockIdx.x;
    int n = g_counts[cls * PAD];
    int start = g_offsets[cls];
    int tid = threadIdx.x;
    int r4 = tid >> 6;   // row slot 0..3
    int c4 = tid & 63;   // float4 column 0..63

    __shared__ float4 s[256];
    const float4* __restrict__ f4 = reinterpret_cast<const float4*>(features);
    const int* __restrict__ ridx = g_rowidx + start;

    float4 a0 = make_float4(0.f, 0.f, 0.f, 0.f);
    float4 a1 = a0, a2 = a0, a3 = a0;
    float4 a4 = a0, a5 = a0, a6 = a0, a7 = a0;

    int i = r4;
    // 8-deep unroll x 4 row slots = 32 rows in flight per block iteration.
    for (; i + 28 < n; i += 32) {
        int i0 = ridx[i];
        int i1 = ridx[i + 4];
        int i2 = ridx[i + 8];
        int i3 = ridx[i + 12];
        int i4 = ridx[i + 16];
        int i5 = ridx[i + 20];
        int i6 = ridx[i + 24];
        int i7 = ridx[i + 28];
        float4 v0 = f4[(size_t)i0 * 64 + c4];
        float4 v1 = f4[(size_t)i1 * 64 + c4];
        float4 v2 = f4[(size_t)i2 * 64 + c4];
        float4 v3 = f4[(size_t)i3 * 64 + c4];
        float4 v4 = f4[(size_t)i4 * 64 + c4];
        float4 v5 = f4[(size_t)i5 * 64 + c4];
        float4 v6 = f4[(size_t)i6 * 64 + c4];
        float4 v7 = f4[(size_t)i7 * 64 + c4];
        F4ADD(a0, v0); F4ADD(a1, v1); F4ADD(a2, v2); F4ADD(a3, v3);
        F4ADD(a4, v4); F4ADD(a5, v5); F4ADD(a6, v6); F4ADD(a7, v7);
    }
    for (; i < n; i += 4) {
        int r = ridx[i];
        float4 v = f4[(size_t)r * 64 + c4];
        F4ADD(a0, v);
    }
    F4ADD(a0, a1); F4ADD(a2, a3); F4ADD(a4, a5); F4ADD(a6, a7);
    F4ADD(a0, a2); F4ADD(a4, a6);
    F4ADD(a0, a4);

    s[tid] = a0;
    __syncthreads();

    if (tid < 64) {
        float4 t0 = s[tid];
        float4 t1 = s[tid + 64];
        float4 t2 = s[tid + 128];
        float4 t3 = s[tid + 192];
        F4ADD(t0, t1); F4ADD(t2, t3); F4ADD(t0, t2);

        float4 c = reinterpret_cast<const float4*>(centers)[(size_t)cls * 64 + tid];
        float4 o;
        if (n > 0) {
            float scale = ALPHA / (float)n;   // ALPHA * mean
            o.x = (1.0f - ALPHA) * c.x + scale * t0.x;
            o.y = (1.0f - ALPHA) * c.y + scale * t0.y;
            o.z = (1.0f - ALPHA) * c.z + scale * t0.z;
            o.w = (1.0f - ALPHA) * c.w + scale * t0.w;
        } else {
            o = c;
        }
        reinterpret_cast<float4*>(out)[(size_t)cls * 64 + tid] = o;
    }
}

// ---------------------------------------------------------------------------
// Launch: features f32 [N,256], labels i32 [N], centers f32 [1000,256].
// ---------------------------------------------------------------------------
extern "C" void kernel_launch(void* const* d_in, const int* in_sizes, int n_in,
                              void* d_out, int out_size) {
    const float* features = (const float*)d_in[0];
    const int* labels     = (const int*)d_in[1];
    const float* centers  = (const float*)d_in[2];
    float* out            = (float*)d_out;

    zero_kernel<<<(NUM_CLASSES * PAD + 255) / 256, 256>>>();
    hist_kernel<<<(N_ROWS + 255) / 256, 256>>>(labels);
    scan_kernel<<<1, 1024>>>();
    scatter_kernel<<<(N_ROWS + 255) / 256, 256>>>(labels);
    sum_ema_kernel<<<NUM_CLASSES, 256>>>(features, centers, out);
}

// round 6
// speedup vs baseline: 1.6023x; 1.0696x over previous
#include <cuda_runtime.h>
#include <cuda_bf16.h>
#include <cstdint>

#define NUM_CLASSES 1000
#define FEAT_DIM    256
#define N_ROWS      262144
#define ALPHA       0.5f
#define PAD         32          // one counter per 128-byte L2 line

// Scratch (device globals — no allocation allowed).
__device__ int g_cursors[NUM_CLASSES * PAD];   // padded; doubles as histogram
__device__ int g_offsets[NUM_CLASSES];
__device__ int g_counts[NUM_CLASSES];
__device__ int g_rank[N_ROWS];
__device__ int g_rowidx[N_ROWS];

// ---------------------------------------------------------------------------
// K1: zero the padded cursors (128 KB).
// ---------------------------------------------------------------------------
__global__ void zero_kernel() {
    int i = blockIdx.x * blockDim.x + threadIdx.x;
    if (i < NUM_CLASSES * PAD) g_cursors[i] = 0;
}

// ---------------------------------------------------------------------------
// K2: single atomic pass — within-class rank. Cursors end up = histogram.
// ---------------------------------------------------------------------------
__global__ void rank_kernel(const int* __restrict__ labels) {
    int i = blockIdx.x * blockDim.x + threadIdx.x;
    if (i < N_ROWS) {
        int cls = labels[i];
        g_rank[i] = atomicAdd(&g_cursors[cls * PAD], 1);
    }
}

// ---------------------------------------------------------------------------
// K3: exclusive prefix scan over 1000 counts (single block, 1024 threads).
// ---------------------------------------------------------------------------
__global__ void scan_kernel() {
    __shared__ int sc[1024];
    int tid = threadIdx.x;
    int val = (tid < NUM_CLASSES) ? g_cursors[tid * PAD] : 0;
    sc[tid] = val;
    __syncthreads();
#pragma unroll
    for (int off = 1; off < 1024; off <<= 1) {
        int t = (tid >= off) ? sc[tid - off] : 0;
        __syncthreads();
        sc[tid] += t;
        __syncthreads();
    }
    if (tid < NUM_CLASSES) {
        g_offsets[tid] = sc[tid] - val;   // exclusive scan
        g_counts[tid] = val;
    }
}

// ---------------------------------------------------------------------------
// K4: place — atomic-free scatter of row indices into class-sorted order.
// ---------------------------------------------------------------------------
__global__ void place_kernel(const int* __restrict__ labels) {
    int i = blockIdx.x * blockDim.x + threadIdx.x;
    if (i < N_ROWS) {
        int pos = g_offsets[labels[i]] + g_rank[i];
        g_rowidx[pos] = i;
    }
}

// ---------------------------------------------------------------------------
// K5: gather-sum + fused mean/EMA. 500 blocks x 2 classes = single wave at
// 4 blocks/SM. 256 threads: tid -> (row slot r4 0..3, float4 column c4 0..63).
// ---------------------------------------------------------------------------
#define F4ADD(a, b) { (a).x += (b).x; (a).y += (b).y; (a).z += (b).z; (a).w += (b).w; }

__global__ void __launch_bounds__(256, 4)
sum_ema_kernel(const float* __restrict__ features,
               const float* __restrict__ centers,
               float* __restrict__ out) {
    int tid = threadIdx.x;
    int r4 = tid >> 6;   // row slot 0..3
    int c4 = tid & 63;   // float4 column 0..63

    __shared__ float4 s[256];
    const float4* __restrict__ f4 = reinterpret_cast<const float4*>(features);

#pragma unroll 1
    for (int sub = 0; sub < 2; sub++) {
        int cls = blockIdx.x * 2 + sub;
        int n = g_counts[cls];
        const int* __restrict__ ridx = g_rowidx + g_offsets[cls];

        float4 a0 = make_float4(0.f, 0.f, 0.f, 0.f);
        float4 a1 = a0, a2 = a0, a3 = a0;

        int i = r4;
        // 4-deep unroll x 4 row slots = 16 rows in flight per block iter.
        for (; i + 12 < n; i += 16) {
            int i0 = ridx[i];
            int i1 = ridx[i + 4];
            int i2 = ridx[i + 8];
            int i3 = ridx[i + 12];
            float4 v0 = f4[(size_t)i0 * 64 + c4];
            float4 v1 = f4[(size_t)i1 * 64 + c4];
            float4 v2 = f4[(size_t)i2 * 64 + c4];
            float4 v3 = f4[(size_t)i3 * 64 + c4];
            F4ADD(a0, v0); F4ADD(a1, v1); F4ADD(a2, v2); F4ADD(a3, v3);
        }
        for (; i < n; i += 4) {
            int r = ridx[i];
            float4 v = f4[(size_t)r * 64 + c4];
            F4ADD(a0, v);
        }
        F4ADD(a0, a1); F4ADD(a2, a3); F4ADD(a0, a2);

        s[tid] = a0;
        __syncthreads();

        if (tid < 64) {
            float4 t0 = s[tid];
            float4 t1 = s[tid + 64];
            float4 t2 = s[tid + 128];
            float4 t3 = s[tid + 192];
            F4ADD(t0, t1); F4ADD(t2, t3); F4ADD(t0, t2);

            float4 c = reinterpret_cast<const float4*>(centers)[(size_t)cls * 64 + tid];
            float4 o;
            if (n > 0) {
                float scale = ALPHA / (float)n;   // ALPHA * mean
                o.x = (1.0f - ALPHA) * c.x + scale * t0.x;
                o.y = (1.0f - ALPHA) * c.y + scale * t0.y;
                o.z = (1.0f - ALPHA) * c.z + scale * t0.z;
                o.w = (1.0f - ALPHA) * c.w + scale * t0.w;
            } else {
                o = c;
            }
            reinterpret_cast<float4*>(out)[(size_t)cls * 64 + tid] = o;
        }
        __syncthreads();   // smem reuse safety for second class
    }
}

// ---------------------------------------------------------------------------
// Launch: features f32 [N,256], labels i32 [N], centers f32 [1000,256].
// ---------------------------------------------------------------------------
extern "C" void kernel_launch(void* const* d_in, const int* in_sizes, int n_in,
                              void* d_out, int out_size) {
    const float* features = (const float*)d_in[0];
    const int* labels     = (const int*)d_in[1];
    const float* centers  = (const float*)d_in[2];
    float* out            = (float*)d_out;

    zero_kernel<<<(NUM_CLASSES * PAD + 255) / 256, 256>>>();
    rank_kernel<<<(N_ROWS + 255) / 256, 256>>>(labels);
    scan_kernel<<<1, 1024>>>();
    place_kernel<<<(N_ROWS + 255) / 256, 256>>>(labels);
    sum_ema_kernel<<<NUM_CLASSES / 2, 256>>>(features, centers, out);
}